// round 16
// baseline (speedup 1.0000x reference)
#include <cuda_runtime.h>

#define NTH 256
#define TNTH 256
#define SBM 28      // samples per main CTA (8 warps: 4,4,4,4,3,3,3,3)
#define NBLK 147
#define SB 32       // tail batch tile
#define BSZ 4096
#define ZSTR 34     // P1 / tail staging stride

// ---------------- shared layout (float offsets), main kernel ----------------
#define OFF_WS   0        // 32768 : weight tile up to 128x256
#define OFF_ZIN  32768    // 4096  : 8 warps x zin[128][4]  (also P1 staging)
#define OFF_CB   36864    // 4096  : 2 layers x 32 x 64 c-state
#define OFF_HB   40960    // 4096  : 2 layers x 32 x 64 h-final
#define OFF_EMB  45056    // 6144  : emb 12 x 512
#define OFF_BIAS 51200    // 256
#define OFF_GAM  51456    // 64
#define OFF_BET  51520    // 64
#define OFF_CTX  51584    // 768 ints
#define SMEM_MAIN (52352 * 4)

// tail shared layout (float offsets)
#define T_WS  0
#define T_ZIN 16384
#define T_TB  18560
#define SMEM_TAIL (18816 * 4)

#define TGRID 444
#define TMICRO 6144

__device__ float g_zbuf[12 * BSZ * 64];

typedef unsigned long long u64t;

__device__ __forceinline__ u64t pack2(float x) {
    u64t r; unsigned u = __float_as_uint(x);
    asm("mov.b64 %0, {%1, %1};" : "=l"(r) : "r"(u));
    return r;
}
__device__ __forceinline__ void fma2(u64t& a, u64t b, u64t c) {
    asm("fma.rn.f32x2 %0, %1, %2, %3;" : "=l"(a) : "l"(b), "l"(c), "l"(a));
}
__device__ __forceinline__ float2 unpack2(u64t v) {
    unsigned lo, hi;
    asm("mov.b64 {%0, %1}, %2;" : "=r"(lo), "=r"(hi) : "l"(v));
    return make_float2(__uint_as_float(lo), __uint_as_float(hi));
}
__device__ __forceinline__ float ftanh_(float x) {
    float r; asm("tanh.approx.f32 %0, %1;" : "=f"(r) : "f"(x)); return r;
}
__device__ __forceinline__ float fsig(float x) {
    return fmaf(0.5f, ftanh_(0.5f * x), 0.5f);
}

__device__ __forceinline__ void stage_w(float* dst, const float* src, int n_floats)
{
    const float4* s4 = (const float4*)src;
    float4* d4 = (float4*)dst;
    for (int i = threadIdx.x; i < (n_floats >> 2); i += NTH) d4[i] = s4[i];
}

// no-op kernel: shifts the ncu -s 5 -c 1 capture window onto k_main
extern "C" __global__ void k_noop() {}

// GEMM over k-range [k0,k1): acc[s][g] += zin4[k][s] * W[k][64g + 2lane ..]
template<int NS>
__device__ __forceinline__ void gemm_rng(const float* __restrict__ zin4,
                                         const float* __restrict__ Ws,
                                         int lane, u64t (&acc)[NS][4],
                                         int k0, int k1)
{
    #pragma unroll 4
    for (int k = k0; k < k1; k++) {
        float4 zq = *(const float4*)(zin4 + (k << 2));
        float zs[4] = {zq.x, zq.y, zq.z, zq.w};
        const u64t* wr = (const u64t*)(Ws + (k << 8)) + lane;
        u64t w0 = wr[0], w1 = wr[32], w2 = wr[64], w3 = wr[96];
        #pragma unroll
        for (int s = 0; s < NS; s++) {
            u64t zp = pack2(zs[s]);
            fma2(acc[s][0], zp, w0); fma2(acc[s][1], zp, w1);
            fma2(acc[s][2], zp, w2); fma2(acc[s][3], zp, w3);
        }
    }
}

// One layer, 12 timesteps, ONE WARP handles ns (<= NS) samples end-to-end.
// SKEW=false: [G(t) | E(t)] monolithic.  SKEW=true (K=128): [Gh(t) | E(t) | Gz(t+1)]
template<int K, int ZW, int NS, bool SKEW>
__device__ void warp_cell(float* __restrict__ zin4, const float* __restrict__ Ws,
                          const float* __restrict__ bias_s, const float* __restrict__ gam_s,
                          const float* __restrict__ bet_s, const float* __restrict__ emb_s,
                          const int* __restrict__ ctx_s, float* __restrict__ cbuf,
                          float* __restrict__ hbuf, int gb, int sb, int ns,
                          int ctx_off, int lane)
{
    const int l2 = lane << 1;
    float2 bv[4];
    float c0r[NS], c1r[NS];
    float ga0 = 0, ga1 = 0, be0 = 0, be1 = 0;

    if (ns > 0) {
        #pragma unroll
        for (int g = 0; g < 4; g++) bv[g] = *(const float2*)(bias_s + (g << 6) + l2);
        ga0 = gam_s[l2]; ga1 = gam_s[l2 + 1];
        be0 = bet_s[l2]; be1 = bet_s[l2 + 1];
        #pragma unroll
        for (int si = 0; si < NS; si++) {
            if (si >= ns) break;
            float2 cv = *(const float2*)(cbuf + ((sb + si) << 6) + l2);
            c0r[si] = cv.x; c1r[si] = cv.y;
            float2 hv = *(const float2*)(hbuf + ((sb + si) << 6) + l2);
            zin4[((K - 64 + l2) << 2) + si]     = hv.x;
            zin4[((K - 64 + l2 + 1) << 2) + si] = hv.y;
        }
        if (K == 128) {
            int s = lane >> 3, k8 = (lane & 7) << 3;
            if (s < ns) {
                const float* zsrc = g_zbuf + ((size_t)(gb + sb + s)) * 64 + k8;
                float4 a = *(const float4*)(zsrc);
                float4 b = *(const float4*)(zsrc + 4);
                zin4[((k8 + 0) << 2) + s] = a.x; zin4[((k8 + 1) << 2) + s] = a.y;
                zin4[((k8 + 2) << 2) + s] = a.z; zin4[((k8 + 3) << 2) + s] = a.w;
                zin4[((k8 + 4) << 2) + s] = b.x; zin4[((k8 + 5) << 2) + s] = b.y;
                zin4[((k8 + 6) << 2) + s] = b.z; zin4[((k8 + 7) << 2) + s] = b.w;
            }
        }
    }
    __syncwarp();
    if (ns == 0) return;

    u64t accz[NS][4];
    if (SKEW && K == 128) {
        #pragma unroll
        for (int s = 0; s < NS; s++)
            accz[s][0] = accz[s][1] = accz[s][2] = accz[s][3] = 0ull;
        gemm_rng<NS>(zin4, Ws, lane, accz, 0, 64);
    }

    for (int t = 0; t < 12; t++) {
        float4 za, zb;
        const int spf = lane >> 3, k8 = (lane & 7) << 3;
        const bool zv = (K == 128) && (t < 11) && (spf < ns);
        if (zv) {
            const float* zsrc = g_zbuf + ((size_t)(t + 1) * BSZ + gb + sb + spf) * 64 + k8;
            za = *(const float4*)(zsrc);
            zb = *(const float4*)(zsrc + 4);
        }

        u64t acc[NS][4];
        if (SKEW && K == 128) {
            #pragma unroll
            for (int s = 0; s < NS; s++) {
                acc[s][0] = accz[s][0]; acc[s][1] = accz[s][1];
                acc[s][2] = accz[s][2]; acc[s][3] = accz[s][3];
            }
            gemm_rng<NS>(zin4, Ws, lane, acc, 64, 128);   // Gh(t)
        } else {
            #pragma unroll
            for (int s = 0; s < NS; s++)
                acc[s][0] = acc[s][1] = acc[s][2] = acc[s][3] = 0ull;
            gemm_rng<NS>(zin4, Ws, lane, acc, 0, K);       // full G(t)
        }

        if (zv) {
            zin4[((k8 + 0) << 2) + spf] = za.x; zin4[((k8 + 1) << 2) + spf] = za.y;
            zin4[((k8 + 2) << 2) + spf] = za.z; zin4[((k8 + 3) << 2) + spf] = za.w;
            zin4[((k8 + 4) << 2) + spf] = zb.x; zin4[((k8 + 5) << 2) + spf] = zb.y;
            zin4[((k8 + 6) << 2) + spf] = zb.z; zin4[((k8 + 7) << 2) + spf] = zb.w;
        }
        __syncwarp();

        float2 ua[NS][4], ub[NS][4];
        #pragma unroll
        for (int si = 0; si < NS; si++) {
            if (si >= ns) break;
            const float* up = emb_s + (ctx_s[(sb + si) * 24 + ctx_off + t] << 9);
            #pragma unroll
            for (int g = 0; g < 4; g++) {
                ua[si][g] = *(const float2*)(up + (g << 6) + l2);
                ub[si][g] = *(const float2*)(up + 256 + (g << 6) + l2);
            }
        }

        #pragma unroll
        for (int si = 0; si < NS; si++) {
            if (si >= ns) break;
            float v[8];
            #pragma unroll
            for (int g = 0; g < 4; g++) {
                float2 r = unpack2(acc[si][g]);
                v[2 * g]     = r.x + bv[g].x;
                v[2 * g + 1] = r.y + bv[g].y;
            }

            float mean[4], inv[4];
            #pragma unroll
            for (int g = 0; g < 4; g++) {
                float ss = v[2 * g] + v[2 * g + 1];
                float q  = v[2 * g] * v[2 * g] + v[2 * g + 1] * v[2 * g + 1];
                #pragma unroll
                for (int o = 16; o > 0; o >>= 1) {
                    ss += __shfl_xor_sync(0xffffffffu, ss, o);
                    q  += __shfl_xor_sync(0xffffffffu, q, o);
                }
                float mu = ss * 0.015625f;
                mean[g] = mu;
                inv[g]  = rsqrtf(fmaxf(q * 0.015625f - mu * mu, 0.0f) + 1e-5f);
            }

            float zf[8];
            #pragma unroll
            for (int g = 0; g < 4; g++) {
                zf[2 * g]     = (v[2 * g]     - mean[g]) * inv[g] * (1.0f + ua[si][g].x) + ub[si][g].x;
                zf[2 * g + 1] = (v[2 * g + 1] - mean[g]) * inv[g] * (1.0f + ua[si][g].y) + ub[si][g].y;
            }

            float cn0 = fsig(zf[2]) * c0r[si] + fsig(zf[0]) * ftanh_(zf[6]);
            float cn1 = fsig(zf[3]) * c1r[si] + fsig(zf[1]) * ftanh_(zf[7]);

            float ss = cn0 + cn1, q = cn0 * cn0 + cn1 * cn1;
            #pragma unroll
            for (int o = 16; o > 0; o >>= 1) {
                ss += __shfl_xor_sync(0xffffffffu, ss, o);
                q  += __shfl_xor_sync(0xffffffffu, q, o);
            }
            float mu = ss * 0.015625f;
            float rs = rsqrtf(fmaxf(q * 0.015625f - mu * mu, 0.0f) + 1e-5f);

            float hn0 = fsig(zf[4]) * ftanh_((cn0 - mu) * rs * ga0 + be0);
            float hn1 = fsig(zf[5]) * ftanh_((cn1 - mu) * rs * ga1 + be1);

            c0r[si] = cn0; c1r[si] = cn1;

            zin4[((K - 64 + l2) << 2) + si]     = hn0;
            zin4[((K - 64 + l2 + 1) << 2) + si] = hn1;

            if (t == 11) {
                *(float2*)(hbuf + ((sb + si) << 6) + l2) = make_float2(hn0, hn1);
                *(float2*)(cbuf + ((sb + si) << 6) + l2) = make_float2(cn0, cn1);
            }

            if (ZW == 1) {
                float* zp = g_zbuf + ((size_t)t * BSZ + gb + sb + si) * 64 + l2;
                float2 old = *(float2*)zp;
                *(float2*)zp = make_float2(old.x + hn0, old.y + hn1);
            } else if (ZW == 2) {
                float* zp = g_zbuf + ((size_t)t * BSZ + gb + sb + si) * 64 + l2;
                *(float2*)zp = make_float2(hn0, hn1);
            }
        }
        __syncwarp();

        if (SKEW && K == 128 && t < 11) {
            #pragma unroll
            for (int s = 0; s < NS; s++)
                accz[s][0] = accz[s][1] = accz[s][2] = accz[s][3] = 0ull;
            gemm_rng<NS>(zin4, Ws, lane, accz, 0, 64);
        }
    }
}

extern "C" __global__ void __launch_bounds__(NTH, 1)
k_main(const float* __restrict__ x, const int* __restrict__ context,
       const float* __restrict__ tlW, const float* __restrict__ tlb,
       const float* __restrict__ encW, const float* __restrict__ encb,
       const float* __restrict__ encg, const float* __restrict__ encbe,
       const float* __restrict__ dec0W, const float* __restrict__ dec0b,
       const float* __restrict__ dec0g, const float* __restrict__ dec0be,
       const float* __restrict__ decW, const float* __restrict__ decb,
       const float* __restrict__ decg, const float* __restrict__ decbe,
       const float* __restrict__ emb)
{
    extern __shared__ float sm[];
    const int tid  = threadIdx.x;
    const int lane = tid & 31;
    const int wid  = tid >> 5;
    const int gb   = blockIdx.x * SBM;
    const int M    = min(SBM, BSZ - gb);

    const int sbw = (wid < 4) ? (wid << 2) : (16 + 3 * (wid - 4));
    const int nsw_full = (wid < 4) ? 4 : 3;
    int ns = M - sbw; if (ns < 0) ns = 0; if (ns > nsw_full) ns = nsw_full;

    float* Ws    = sm + OFF_WS;
    float* zin4  = sm + OFF_ZIN + (wid << 9);
    float* zin_p = sm + OFF_ZIN;
    int*   ctx_s = (int*)(sm + OFF_CTX);

    for (int i = tid; i < M * 24; i += NTH) ctx_s[i] = context[gb * 24 + i];
    for (int i = tid; i < 8192; i += NTH) sm[OFF_CB + i] = 0.0f;
    stage_w(sm + OFF_EMB, emb, 6144);
    stage_w(Ws, tlW, 4096);
    for (int i = tid; i < 64; i += NTH) sm[OFF_BIAS + i] = tlb[i];
    __syncthreads();

    // P1
    {
        const int n4 = (tid & 15) << 2;
        const int mi = tid >> 4;
        const int npairs = (M + 1) >> 1;
        for (int t = 0; t < 12; t++) {
            for (int i = tid; i < M * 16; i += NTH) {
                int m = i >> 4, k4 = (i & 15) << 2;
                float4 v = *(const float4*)(x + (size_t)(gb + m) * 768 + t * 64 + k4);
                zin_p[(k4 + 0) * ZSTR + m] = v.x;
                zin_p[(k4 + 1) * ZSTR + m] = v.y;
                zin_p[(k4 + 2) * ZSTR + m] = v.z;
                zin_p[(k4 + 3) * ZSTR + m] = v.w;
            }
            __syncthreads();
            if (mi < npairs) {
                u64t a0 = 0, a1 = 0, a2 = 0, a3 = 0;
                #pragma unroll 8
                for (int k = 0; k < 64; k++) {
                    u64t zz = *(const u64t*)(zin_p + k * ZSTR + (mi << 1));
                    float4 w = *(const float4*)(Ws + (k << 6) + n4);
                    fma2(a0, zz, pack2(w.x));
                    fma2(a1, zz, pack2(w.y));
                    fma2(a2, zz, pack2(w.z));
                    fma2(a3, zz, pack2(w.w));
                }
                float4 bvv = *(const float4*)(sm + OFF_BIAS + n4);
                float2 r0 = unpack2(a0), r1 = unpack2(a1), r2 = unpack2(a2), r3 = unpack2(a3);
                float* zp0 = g_zbuf + ((size_t)t * BSZ + gb + (mi << 1)) * 64 + n4;
                *(float4*)(zp0) = make_float4(r0.x + bvv.x, r1.x + bvv.y, r2.x + bvv.z, r3.x + bvv.w);
                if ((mi << 1) + 1 < M)
                    *(float4*)(zp0 + 64) = make_float4(r0.y + bvv.x, r1.y + bvv.y, r2.y + bvv.z, r3.y + bvv.w);
            }
            __syncthreads();
        }
    }

    float* cb0 = sm + OFF_CB;
    float* cb1 = sm + OFF_CB + 2048;
    float* hb0 = sm + OFF_HB;
    float* hb1 = sm + OFF_HB + 2048;
    const float* emb_s = sm + OFF_EMB;

    // P2
    stage_w(Ws, encW, 32768);
    stage_w(sm + OFF_BIAS, encb, 256);
    for (int i = tid; i < 64; i += NTH) { sm[OFF_GAM + i] = encg[i]; sm[OFF_BET + i] = encbe[i]; }
    __syncthreads();
    if (wid < 4)
        warp_cell<128, 1, 4, false>(zin4, Ws, sm + OFF_BIAS, sm + OFF_GAM, sm + OFF_BET, emb_s,
                                    ctx_s, cb0, hb0, gb, sbw, ns, 0, lane);
    else
        warp_cell<128, 1, 3, true>(zin4, Ws, sm + OFF_BIAS, sm + OFF_GAM, sm + OFF_BET, emb_s,
                                   ctx_s, cb0, hb0, gb, sbw, ns, 0, lane);
    __syncthreads();

    // P3
    stage_w(Ws, encW + 32768, 32768);
    stage_w(sm + OFF_BIAS, encb + 256, 256);
    for (int i = tid; i < 64; i += NTH) { sm[OFF_GAM + i] = encg[64 + i]; sm[OFF_BET + i] = encbe[64 + i]; }
    __syncthreads();
    if (wid < 4)
        warp_cell<128, 0, 4, false>(zin4, Ws, sm + OFF_BIAS, sm + OFF_GAM, sm + OFF_BET, emb_s,
                                    ctx_s, cb1, hb1, gb, sbw, ns, 0, lane);
    else
        warp_cell<128, 0, 3, true>(zin4, Ws, sm + OFF_BIAS, sm + OFF_GAM, sm + OFF_BET, emb_s,
                                   ctx_s, cb1, hb1, gb, sbw, ns, 0, lane);
    __syncthreads();

    // P4
    stage_w(Ws, dec0W, 16384);
    stage_w(sm + OFF_BIAS, dec0b, 256);
    for (int i = tid; i < 64; i += NTH) { sm[OFF_GAM + i] = dec0g[i]; sm[OFF_BET + i] = dec0be[i]; }
    __syncthreads();
    if (wid < 4)
        warp_cell<64, 2, 4, false>(zin4, Ws, sm + OFF_BIAS, sm + OFF_GAM, sm + OFF_BET, emb_s,
                                   ctx_s, cb0, hb0, gb, sbw, ns, 12, lane);
    else
        warp_cell<64, 2, 3, false>(zin4, Ws, sm + OFF_BIAS, sm + OFF_GAM, sm + OFF_BET, emb_s,
                                   ctx_s, cb0, hb0, gb, sbw, ns, 12, lane);
    __syncthreads();

    // P5
    stage_w(Ws, decW, 32768);
    stage_w(sm + OFF_BIAS, decb, 256);
    for (int i = tid; i < 64; i += NTH) { sm[OFF_GAM + i] = decg[i]; sm[OFF_BET + i] = decbe[i]; }
    __syncthreads();
    if (wid < 4)
        warp_cell<128, 1, 4, false>(zin4, Ws, sm + OFF_BIAS, sm + OFF_GAM, sm + OFF_BET, emb_s,
                                    ctx_s, cb1, hb1, gb, sbw, ns, 12, lane);
    else
        warp_cell<128, 1, 3, true>(zin4, Ws, sm + OFF_BIAS, sm + OFF_GAM, sm + OFF_BET, emb_s,
                                   ctx_s, cb1, hb1, gb, sbw, ns, 12, lane);
}

// ============================================================================
// k_tail: persistent single wave, 444 CTAs (at the f32x2 rt-3 roofline).
// ============================================================================
extern "C" __global__ void __launch_bounds__(TNTH, 3)
k_tail(const float* __restrict__ tailW, const float* __restrict__ tailb,
       float* __restrict__ out)
{
    extern __shared__ float sm[];
    float* Ws  = sm + T_WS;
    float* zin = sm + T_ZIN;
    float* tb  = sm + T_TB;
    const int tid = threadIdx.x;
    const int ty  = tid >> 6;
    const int tx  = tid & 63;

    const int p      = blockIdx.x;
    const int mstart = (p * TMICRO) / TGRID;
    const int mend   = ((p + 1) * TMICRO) / TGRID;
    int cur = -1;

    const int m0s = tid >> 4, k40 = (tid & 15) << 2;
    const int i1 = tid + 256;
    const int m1s = i1 >> 4, k41 = (i1 & 15) << 2;

    float4 pf0, pf1;
    {
        int t0 = mstart % 12, job = mstart / 12, bt = job & 127;
        const float* src = g_zbuf + ((size_t)t0 * BSZ + bt * SB) * 64;
        pf0 = *(const float4*)(src + m0s * 64 + k40);
        pf1 = *(const float4*)(src + m1s * 64 + k41);
    }

    for (int mi = mstart; mi < mend; mi++) {
        const int t     = mi % 12;
        const int job   = mi / 12;
        const int gb    = (job & 127) * SB;
        const int ch    = job >> 7;

        if (ch != cur) {
            for (int i = tid; i < 16384; i += TNTH) {
                int k = i >> 8, n = i & 255;
                Ws[i] = tailW[((ch << 2) + (n >> 6)) * 4096 + (k << 6) + (n & 63)];
            }
            for (int i = tid; i < 256; i += TNTH)
                tb[i] = tailb[((ch << 2) + (i >> 6)) * 64 + (i & 63)];
            cur = ch;
        }

        zin[(k40 + 0) * ZSTR + m0s] = pf0.x;
        zin[(k40 + 1) * ZSTR + m0s] = pf0.y;
        zin[(k40 + 2) * ZSTR + m0s] = pf0.z;
        zin[(k40 + 3) * ZSTR + m0s] = pf0.w;
        zin[(k41 + 0) * ZSTR + m1s] = pf1.x;
        zin[(k41 + 1) * ZSTR + m1s] = pf1.y;
        zin[(k41 + 2) * ZSTR + m1s] = pf1.z;
        zin[(k41 + 3) * ZSTR + m1s] = pf1.w;

        if (mi + 1 < mend) {
            int tn = (mi + 1) % 12, jn = (mi + 1) / 12, btn = jn & 127;
            const float* src = g_zbuf + ((size_t)tn * BSZ + btn * SB) * 64;
            pf0 = *(const float4*)(src + m0s * 64 + k40);
            pf1 = *(const float4*)(src + m1s * 64 + k41);
        }
        __syncthreads();

        u64t acc[4][4];
        #pragma unroll
        for (int q = 0; q < 4; q++)
            acc[q][0] = acc[q][1] = acc[q][2] = acc[q][3] = 0ull;

        #pragma unroll 8
        for (int k = 0; k < 64; k++) {
            const u64t* zp = (const u64t*)(zin + k * ZSTR + (ty << 3));
            u64t z0 = zp[0], z1 = zp[1], z2 = zp[2], z3 = zp[3];
            float4 w = *(const float4*)(Ws + (k << 8) + (tx << 2));
            u64t w0 = pack2(w.x), w1 = pack2(w.y), w2 = pack2(w.z), w3 = pack2(w.w);
            fma2(acc[0][0], z0, w0); fma2(acc[0][1], z0, w1); fma2(acc[0][2], z0, w2); fma2(acc[0][3], z0, w3);
            fma2(acc[1][0], z1, w0); fma2(acc[1][1], z1, w1); fma2(acc[1][2], z1, w2); fma2(acc[1][3], z1, w3);
            fma2(acc[2][0], z2, w0); fma2(acc[2][1], z2, w1); fma2(acc[2][2], z2, w2); fma2(acc[2][3], z2, w3);
            fma2(acc[3][0], z3, w0); fma2(acc[3][1], z3, w1); fma2(acc[3][2], z3, w2); fma2(acc[3][3], z3, w3);
        }

        float4 bvv = *(const float4*)(tb + (tx << 2));
        int nt = (cur << 2) + (tx >> 4);
        int d  = (tx << 2) & 63;
        #pragma unroll
        for (int q = 0; q < 4; q++) {
            float2 r0 = unpack2(acc[q][0]), r1 = unpack2(acc[q][1]);
            float2 r2 = unpack2(acc[q][2]), r3 = unpack2(acc[q][3]);
            int mm = (ty << 3) + (q << 1);
            float* op = out + (size_t)(gb + mm) * 12288 + nt * 768 + t * 64 + d;
            *(float4*)(op)         = make_float4(r0.x + bvv.x, r1.x + bvv.y, r2.x + bvv.z, r3.x + bvv.w);
            *(float4*)(op + 12288) = make_float4(r0.y + bvv.x, r1.y + bvv.y, r2.y + bvv.z, r3.y + bvv.w);
        }
        __syncthreads();
    }
}

extern "C" void kernel_launch(void* const* d_in, const int* in_sizes, int n_in,
                              void* d_out, int out_size)
{
    cudaFuncSetAttribute(k_main, cudaFuncAttributeMaxDynamicSharedMemorySize, SMEM_MAIN);
    cudaFuncSetAttribute(k_tail, cudaFuncAttributeMaxDynamicSharedMemorySize, SMEM_TAIL);

    // launch pattern [noop, main, noop, tail]: per replay = 4 launches, so the
    // ncu "-s 5 -c 1" window (6th launch overall) lands on k_main in replay 1.
    k_noop<<<1, 32>>>();

    k_main<<<NBLK, NTH, SMEM_MAIN>>>(
        (const float*)d_in[0],  (const int*)d_in[1],
        (const float*)d_in[2],  (const float*)d_in[3],
        (const float*)d_in[4],  (const float*)d_in[5],
        (const float*)d_in[6],  (const float*)d_in[7],
        (const float*)d_in[8],  (const float*)d_in[9],
        (const float*)d_in[10], (const float*)d_in[11],
        (const float*)d_in[12], (const float*)d_in[13],
        (const float*)d_in[14], (const float*)d_in[15],
        (const float*)d_in[18]);

    k_noop<<<1, 32>>>();

    k_tail<<<TGRID, TNTH, SMEM_TAIL>>>(
        (const float*)d_in[16], (const float*)d_in[17], (float*)d_out);
}

// round 17
// speedup vs baseline: 1.0142x; 1.0142x over previous
#include <cuda_runtime.h>

#define NTH 256
#define TNTH 256
#define SBM 28      // samples per main CTA (8 warps: 4,4,4,4,3,3,3,3)
#define NBLK 147
#define SB 32       // tail batch tile
#define BSZ 4096
#define ZSTR 34     // P1 / tail staging stride

// ---------------- shared layout (float offsets), main kernel ----------------
#define OFF_WS   0        // 32768 : weight tile up to 128x256
#define OFF_ZIN  32768    // 4096  : 8 warps x zin[128][4]  (also P1 staging)
#define OFF_CB   36864    // 4096  : 2 layers x 32 x 64 c-state
#define OFF_HB   40960    // 4096  : 2 layers x 32 x 64 h-final
#define OFF_EMB  45056    // 6144  : emb 12 x 512
#define OFF_BIAS 51200    // 256
#define OFF_GAM  51456    // 64
#define OFF_BET  51520    // 64
#define OFF_CTX  51584    // 768 ints
#define SMEM_MAIN (52352 * 4)

// tail shared layout (float offsets)
#define T_WS  0
#define T_ZIN 16384
#define T_TB  18560
#define SMEM_TAIL (18816 * 4)

#define TGRID 444
#define TMICRO 6144

__device__ float g_zbuf[12 * BSZ * 64];

typedef unsigned long long u64t;

__device__ __forceinline__ u64t pack2(float x) {
    u64t r; unsigned u = __float_as_uint(x);
    asm("mov.b64 %0, {%1, %1};" : "=l"(r) : "r"(u));
    return r;
}
__device__ __forceinline__ void fma2(u64t& a, u64t b, u64t c) {
    asm("fma.rn.f32x2 %0, %1, %2, %3;" : "=l"(a) : "l"(b), "l"(c), "l"(a));
}
__device__ __forceinline__ float2 unpack2(u64t v) {
    unsigned lo, hi;
    asm("mov.b64 {%0, %1}, %2;" : "=r"(lo), "=r"(hi) : "l"(v));
    return make_float2(__uint_as_float(lo), __uint_as_float(hi));
}
__device__ __forceinline__ float ftanh_(float x) {
    float r; asm("tanh.approx.f32 %0, %1;" : "=f"(r) : "f"(x)); return r;
}
__device__ __forceinline__ float fsig(float x) {
    return fmaf(0.5f, ftanh_(0.5f * x), 0.5f);
}

__device__ __forceinline__ void stage_w(float* dst, const float* src, int n_floats)
{
    const float4* s4 = (const float4*)src;
    float4* d4 = (float4*)dst;
    for (int i = threadIdx.x; i < (n_floats >> 2); i += NTH) d4[i] = s4[i];
}

// GEMM over k-range [k0,k1): acc[s][g] += zin4[k][s] * W[k][64g + 2lane ..]
template<int NS>
__device__ __forceinline__ void gemm_rng(const float* __restrict__ zin4,
                                         const float* __restrict__ Ws,
                                         int lane, u64t (&acc)[NS][4],
                                         int k0, int k1)
{
    #pragma unroll 4
    for (int k = k0; k < k1; k++) {
        float4 zq = *(const float4*)(zin4 + (k << 2));
        float zs[4] = {zq.x, zq.y, zq.z, zq.w};
        const u64t* wr = (const u64t*)(Ws + (k << 8)) + lane;
        u64t w0 = wr[0], w1 = wr[32], w2 = wr[64], w3 = wr[96];
        #pragma unroll
        for (int s = 0; s < NS; s++) {
            u64t zp = pack2(zs[s]);
            fma2(acc[s][0], zp, w0); fma2(acc[s][1], zp, w1);
            fma2(acc[s][2], zp, w2); fma2(acc[s][3], zp, w3);
        }
    }
}

// One layer, 12 timesteps, ONE WARP handles ns (<= NS) samples end-to-end.
// Elem phase is SoA-batched across samples: all butterfly levels issued
// together so the 26-cyc shfl latency is paid once, not per sample.
// SKEW=true (K=128): [Gh(t) | E(t) | Gz(t+1)] to anti-phase SMSP partner warps.
template<int K, int ZW, int NS, bool SKEW>
__device__ void warp_cell(float* __restrict__ zin4, const float* __restrict__ Ws,
                          const float* __restrict__ bias_s, const float* __restrict__ gam_s,
                          const float* __restrict__ bet_s, const float* __restrict__ emb_s,
                          const int* __restrict__ ctx_s, float* __restrict__ cbuf,
                          float* __restrict__ hbuf, int gb, int sb, int ns,
                          int ctx_off, int lane)
{
    const int l2 = lane << 1;
    float2 bv[4];
    float c0r[NS], c1r[NS];
    float ga0 = 0, ga1 = 0, be0 = 0, be1 = 0;

    if (ns > 0) {
        #pragma unroll
        for (int g = 0; g < 4; g++) bv[g] = *(const float2*)(bias_s + (g << 6) + l2);
        ga0 = gam_s[l2]; ga1 = gam_s[l2 + 1];
        be0 = bet_s[l2]; be1 = bet_s[l2 + 1];
        #pragma unroll
        for (int si = 0; si < NS; si++) {
            if (si >= ns) break;
            float2 cv = *(const float2*)(cbuf + ((sb + si) << 6) + l2);
            c0r[si] = cv.x; c1r[si] = cv.y;
            float2 hv = *(const float2*)(hbuf + ((sb + si) << 6) + l2);
            zin4[((K - 64 + l2) << 2) + si]     = hv.x;
            zin4[((K - 64 + l2 + 1) << 2) + si] = hv.y;
        }
        if (K == 128) {
            int s = lane >> 3, k8 = (lane & 7) << 3;
            if (s < ns) {
                const float* zsrc = g_zbuf + ((size_t)(gb + sb + s)) * 64 + k8;
                float4 a = *(const float4*)(zsrc);
                float4 b = *(const float4*)(zsrc + 4);
                zin4[((k8 + 0) << 2) + s] = a.x; zin4[((k8 + 1) << 2) + s] = a.y;
                zin4[((k8 + 2) << 2) + s] = a.z; zin4[((k8 + 3) << 2) + s] = a.w;
                zin4[((k8 + 4) << 2) + s] = b.x; zin4[((k8 + 5) << 2) + s] = b.y;
                zin4[((k8 + 6) << 2) + s] = b.z; zin4[((k8 + 7) << 2) + s] = b.w;
            }
        }
    }
    __syncwarp();
    if (ns == 0) return;

    u64t accz[NS][4];
    if (SKEW && K == 128) {
        #pragma unroll
        for (int s = 0; s < NS; s++)
            accz[s][0] = accz[s][1] = accz[s][2] = accz[s][3] = 0ull;
        gemm_rng<NS>(zin4, Ws, lane, accz, 0, 64);
    }

    for (int t = 0; t < 12; t++) {
        // ---- z(t+1) LDG issued early ----
        float4 za, zb;
        const int spf = lane >> 3, k8 = (lane & 7) << 3;
        const bool zv = (K == 128) && (t < 11) && (spf < ns);
        if (zv) {
            const float* zsrc = g_zbuf + ((size_t)(t + 1) * BSZ + gb + sb + spf) * 64 + k8;
            za = *(const float4*)(zsrc);
            zb = *(const float4*)(zsrc + 4);
        }

        // ---- GEMM phase ----
        u64t acc[NS][4];
        if (SKEW && K == 128) {
            #pragma unroll
            for (int s = 0; s < NS; s++) {
                acc[s][0] = accz[s][0]; acc[s][1] = accz[s][1];
                acc[s][2] = accz[s][2]; acc[s][3] = accz[s][3];
            }
            gemm_rng<NS>(zin4, Ws, lane, acc, 64, 128);   // Gh(t)
        } else {
            #pragma unroll
            for (int s = 0; s < NS; s++)
                acc[s][0] = acc[s][1] = acc[s][2] = acc[s][3] = 0ull;
            gemm_rng<NS>(zin4, Ws, lane, acc, 0, K);       // full G(t)
        }

        if (zv) {
            zin4[((k8 + 0) << 2) + spf] = za.x; zin4[((k8 + 1) << 2) + spf] = za.y;
            zin4[((k8 + 2) << 2) + spf] = za.z; zin4[((k8 + 3) << 2) + spf] = za.w;
            zin4[((k8 + 4) << 2) + spf] = zb.x; zin4[((k8 + 5) << 2) + spf] = zb.y;
            zin4[((k8 + 6) << 2) + spf] = zb.z; zin4[((k8 + 7) << 2) + spf] = zb.w;
        }
        __syncwarp();

        // ---- FiLM u (emb in smem) ----
        float2 ua[NS][4], ub[NS][4];
        #pragma unroll
        for (int si = 0; si < NS; si++) {
            if (si >= ns) break;
            const float* up = emb_s + (ctx_s[(sb + si) * 24 + ctx_off + t] << 9);
            #pragma unroll
            for (int g = 0; g < 4; g++) {
                ua[si][g] = *(const float2*)(up + (g << 6) + l2);
                ub[si][g] = *(const float2*)(up + 256 + (g << 6) + l2);
            }
        }

        // ================= elem: SoA-batched across samples =================
        // (1) v = acc + bias for ALL samples
        float v[NS][8];
        #pragma unroll
        for (int si = 0; si < NS; si++) {
            #pragma unroll
            for (int g = 0; g < 4; g++) {
                float2 r = unpack2(acc[si][g]);
                v[si][2 * g]     = r.x + bv[g].x;
                v[si][2 * g + 1] = r.y + bv[g].y;
            }
        }

        // (2) GN4 reductions: all NS*4 (sum, sumsq) pairs, level-by-level
        float sr[NS][4], qr[NS][4];
        #pragma unroll
        for (int si = 0; si < NS; si++) {
            #pragma unroll
            for (int g = 0; g < 4; g++) {
                sr[si][g] = v[si][2 * g] + v[si][2 * g + 1];
                qr[si][g] = v[si][2 * g] * v[si][2 * g] + v[si][2 * g + 1] * v[si][2 * g + 1];
            }
        }
        #pragma unroll
        for (int o = 16; o > 0; o >>= 1) {
            #pragma unroll
            for (int si = 0; si < NS; si++) {
                #pragma unroll
                for (int g = 0; g < 4; g++) {
                    sr[si][g] += __shfl_xor_sync(0xffffffffu, sr[si][g], o);
                    qr[si][g] += __shfl_xor_sync(0xffffffffu, qr[si][g], o);
                }
            }
        }

        // (3) FiLM + gates -> cn for ALL samples
        float cn0[NS], cn1[NS];
        #pragma unroll
        for (int si = 0; si < NS; si++) {
            float zf[8];
            #pragma unroll
            for (int g = 0; g < 4; g++) {
                float mu  = sr[si][g] * 0.015625f;
                float inv = rsqrtf(fmaxf(qr[si][g] * 0.015625f - mu * mu, 0.0f) + 1e-5f);
                zf[2 * g]     = (v[si][2 * g]     - mu) * inv * (1.0f + ua[si][g].x) + ub[si][g].x;
                zf[2 * g + 1] = (v[si][2 * g + 1] - mu) * inv * (1.0f + ua[si][g].y) + ub[si][g].y;
            }
            cn0[si] = fsig(zf[2]) * c0r[si] + fsig(zf[0]) * ftanh_(zf[6]);
            cn1[si] = fsig(zf[3]) * c1r[si] + fsig(zf[1]) * ftanh_(zf[7]);
            // stash o-gate pre-activations in v for reuse after GN1
            v[si][0] = zf[4];
            v[si][1] = zf[5];
        }

        // (4) GN1 reductions batched
        float s2[NS], q2[NS];
        #pragma unroll
        for (int si = 0; si < NS; si++) {
            s2[si] = cn0[si] + cn1[si];
            q2[si] = cn0[si] * cn0[si] + cn1[si] * cn1[si];
        }
        #pragma unroll
        for (int o = 16; o > 0; o >>= 1) {
            #pragma unroll
            for (int si = 0; si < NS; si++) {
                s2[si] += __shfl_xor_sync(0xffffffffu, s2[si], o);
                q2[si] += __shfl_xor_sync(0xffffffffu, q2[si], o);
            }
        }

        // (5) final h + stores (guarded per sample)
        #pragma unroll
        for (int si = 0; si < NS; si++) {
            if (si >= ns) break;
            float mu = s2[si] * 0.015625f;
            float rs = rsqrtf(fmaxf(q2[si] * 0.015625f - mu * mu, 0.0f) + 1e-5f);
            float hn0 = fsig(v[si][0]) * ftanh_((cn0[si] - mu) * rs * ga0 + be0);
            float hn1 = fsig(v[si][1]) * ftanh_((cn1[si] - mu) * rs * ga1 + be1);

            c0r[si] = cn0[si]; c1r[si] = cn1[si];

            zin4[((K - 64 + l2) << 2) + si]     = hn0;
            zin4[((K - 64 + l2 + 1) << 2) + si] = hn1;

            if (t == 11) {
                *(float2*)(hbuf + ((sb + si) << 6) + l2) = make_float2(hn0, hn1);
                *(float2*)(cbuf + ((sb + si) << 6) + l2) = make_float2(cn0[si], cn1[si]);
            }

            if (ZW == 1) {
                float* zp = g_zbuf + ((size_t)t * BSZ + gb + sb + si) * 64 + l2;
                float2 old = *(float2*)zp;
                *(float2*)zp = make_float2(old.x + hn0, old.y + hn1);
            } else if (ZW == 2) {
                float* zp = g_zbuf + ((size_t)t * BSZ + gb + sb + si) * 64 + l2;
                *(float2*)zp = make_float2(hn0, hn1);
            }
        }
        __syncwarp();

        if (SKEW && K == 128 && t < 11) {
            #pragma unroll
            for (int s = 0; s < NS; s++)
                accz[s][0] = accz[s][1] = accz[s][2] = accz[s][3] = 0ull;
            gemm_rng<NS>(zin4, Ws, lane, accz, 0, 64);
        }
    }
}

extern "C" __global__ void __launch_bounds__(NTH, 1)
k_main(const float* __restrict__ x, const int* __restrict__ context,
       const float* __restrict__ tlW, const float* __restrict__ tlb,
       const float* __restrict__ encW, const float* __restrict__ encb,
       const float* __restrict__ encg, const float* __restrict__ encbe,
       const float* __restrict__ dec0W, const float* __restrict__ dec0b,
       const float* __restrict__ dec0g, const float* __restrict__ dec0be,
       const float* __restrict__ decW, const float* __restrict__ decb,
       const float* __restrict__ decg, const float* __restrict__ decbe,
       const float* __restrict__ emb)
{
    extern __shared__ float sm[];
    const int tid  = threadIdx.x;
    const int lane = tid & 31;
    const int wid  = tid >> 5;
    const int gb   = blockIdx.x * SBM;
    const int M    = min(SBM, BSZ - gb);

    const int sbw = (wid < 4) ? (wid << 2) : (16 + 3 * (wid - 4));
    const int nsw_full = (wid < 4) ? 4 : 3;
    int ns = M - sbw; if (ns < 0) ns = 0; if (ns > nsw_full) ns = nsw_full;

    float* Ws    = sm + OFF_WS;
    float* zin4  = sm + OFF_ZIN + (wid << 9);
    float* zin_p = sm + OFF_ZIN;
    int*   ctx_s = (int*)(sm + OFF_CTX);

    for (int i = tid; i < M * 24; i += NTH) ctx_s[i] = context[gb * 24 + i];
    for (int i = tid; i < 8192; i += NTH) sm[OFF_CB + i] = 0.0f;
    stage_w(sm + OFF_EMB, emb, 6144);
    stage_w(Ws, tlW, 4096);
    for (int i = tid; i < 64; i += NTH) sm[OFF_BIAS + i] = tlb[i];
    __syncthreads();

    // P1
    {
        const int n4 = (tid & 15) << 2;
        const int mi = tid >> 4;
        const int npairs = (M + 1) >> 1;
        for (int t = 0; t < 12; t++) {
            for (int i = tid; i < M * 16; i += NTH) {
                int m = i >> 4, k4 = (i & 15) << 2;
                float4 v = *(const float4*)(x + (size_t)(gb + m) * 768 + t * 64 + k4);
                zin_p[(k4 + 0) * ZSTR + m] = v.x;
                zin_p[(k4 + 1) * ZSTR + m] = v.y;
                zin_p[(k4 + 2) * ZSTR + m] = v.z;
                zin_p[(k4 + 3) * ZSTR + m] = v.w;
            }
            __syncthreads();
            if (mi < npairs) {
                u64t a0 = 0, a1 = 0, a2 = 0, a3 = 0;
                #pragma unroll 8
                for (int k = 0; k < 64; k++) {
                    u64t zz = *(const u64t*)(zin_p + k * ZSTR + (mi << 1));
                    float4 w = *(const float4*)(Ws + (k << 6) + n4);
                    fma2(a0, zz, pack2(w.x));
                    fma2(a1, zz, pack2(w.y));
                    fma2(a2, zz, pack2(w.z));
                    fma2(a3, zz, pack2(w.w));
                }
                float4 bvv = *(const float4*)(sm + OFF_BIAS + n4);
                float2 r0 = unpack2(a0), r1 = unpack2(a1), r2 = unpack2(a2), r3 = unpack2(a3);
                float* zp0 = g_zbuf + ((size_t)t * BSZ + gb + (mi << 1)) * 64 + n4;
                *(float4*)(zp0) = make_float4(r0.x + bvv.x, r1.x + bvv.y, r2.x + bvv.z, r3.x + bvv.w);
                if ((mi << 1) + 1 < M)
                    *(float4*)(zp0 + 64) = make_float4(r0.y + bvv.x, r1.y + bvv.y, r2.y + bvv.z, r3.y + bvv.w);
            }
            __syncthreads();
        }
    }

    float* cb0 = sm + OFF_CB;
    float* cb1 = sm + OFF_CB + 2048;
    float* hb0 = sm + OFF_HB;
    float* hb1 = sm + OFF_HB + 2048;
    const float* emb_s = sm + OFF_EMB;

    // P2
    stage_w(Ws, encW, 32768);
    stage_w(sm + OFF_BIAS, encb, 256);
    for (int i = tid; i < 64; i += NTH) { sm[OFF_GAM + i] = encg[i]; sm[OFF_BET + i] = encbe[i]; }
    __syncthreads();
    if (wid < 4)
        warp_cell<128, 1, 4, false>(zin4, Ws, sm + OFF_BIAS, sm + OFF_GAM, sm + OFF_BET, emb_s,
                                    ctx_s, cb0, hb0, gb, sbw, ns, 0, lane);
    else
        warp_cell<128, 1, 3, true>(zin4, Ws, sm + OFF_BIAS, sm + OFF_GAM, sm + OFF_BET, emb_s,
                                   ctx_s, cb0, hb0, gb, sbw, ns, 0, lane);
    __syncthreads();

    // P3
    stage_w(Ws, encW + 32768, 32768);
    stage_w(sm + OFF_BIAS, encb + 256, 256);
    for (int i = tid; i < 64; i += NTH) { sm[OFF_GAM + i] = encg[64 + i]; sm[OFF_BET + i] = encbe[64 + i]; }
    __syncthreads();
    if (wid < 4)
        warp_cell<128, 0, 4, false>(zin4, Ws, sm + OFF_BIAS, sm + OFF_GAM, sm + OFF_BET, emb_s,
                                    ctx_s, cb1, hb1, gb, sbw, ns, 0, lane);
    else
        warp_cell<128, 0, 3, true>(zin4, Ws, sm + OFF_BIAS, sm + OFF_GAM, sm + OFF_BET, emb_s,
                                   ctx_s, cb1, hb1, gb, sbw, ns, 0, lane);
    __syncthreads();

    // P4
    stage_w(Ws, dec0W, 16384);
    stage_w(sm + OFF_BIAS, dec0b, 256);
    for (int i = tid; i < 64; i += NTH) { sm[OFF_GAM + i] = dec0g[i]; sm[OFF_BET + i] = dec0be[i]; }
    __syncthreads();
    if (wid < 4)
        warp_cell<64, 2, 4, false>(zin4, Ws, sm + OFF_BIAS, sm + OFF_GAM, sm + OFF_BET, emb_s,
                                   ctx_s, cb0, hb0, gb, sbw, ns, 12, lane);
    else
        warp_cell<64, 2, 3, false>(zin4, Ws, sm + OFF_BIAS, sm + OFF_GAM, sm + OFF_BET, emb_s,
                                   ctx_s, cb0, hb0, gb, sbw, ns, 12, lane);
    __syncthreads();

    // P5
    stage_w(Ws, decW, 32768);
    stage_w(sm + OFF_BIAS, decb, 256);
    for (int i = tid; i < 64; i += NTH) { sm[OFF_GAM + i] = decg[i]; sm[OFF_BET + i] = decbe[i]; }
    __syncthreads();
    if (wid < 4)
        warp_cell<128, 1, 4, false>(zin4, Ws, sm + OFF_BIAS, sm + OFF_GAM, sm + OFF_BET, emb_s,
                                    ctx_s, cb1, hb1, gb, sbw, ns, 12, lane);
    else
        warp_cell<128, 1, 3, true>(zin4, Ws, sm + OFF_BIAS, sm + OFF_GAM, sm + OFF_BET, emb_s,
                                   ctx_s, cb1, hb1, gb, sbw, ns, 12, lane);
}

// ============================================================================
// k_tail: persistent single wave, 444 CTAs (at the f32x2 rt-3 roofline).
// ============================================================================
extern "C" __global__ void __launch_bounds__(TNTH, 3)
k_tail(const float* __restrict__ tailW, const float* __restrict__ tailb,
       float* __restrict__ out)
{
    extern __shared__ float sm[];
    float* Ws  = sm + T_WS;
    float* zin = sm + T_ZIN;
    float* tb  = sm + T_TB;
    const int tid = threadIdx.x;
    const int ty  = tid >> 6;
    const int tx  = tid & 63;

    const int p      = blockIdx.x;
    const int mstart = (p * TMICRO) / TGRID;
    const int mend   = ((p + 1) * TMICRO) / TGRID;
    int cur = -1;

    const int m0s = tid >> 4, k40 = (tid & 15) << 2;
    const int i1 = tid + 256;
    const int m1s = i1 >> 4, k41 = (i1 & 15) << 2;

    float4 pf0, pf1;
    {
        int t0 = mstart % 12, job = mstart / 12, bt = job & 127;
        const float* src = g_zbuf + ((size_t)t0 * BSZ + bt * SB) * 64;
        pf0 = *(const float4*)(src + m0s * 64 + k40);
        pf1 = *(const float4*)(src + m1s * 64 + k41);
    }

    for (int mi = mstart; mi < mend; mi++) {
        const int t     = mi % 12;
        const int job   = mi / 12;
        const int gb    = (job & 127) * SB;
        const int ch    = job >> 7;

        if (ch != cur) {
            for (int i = tid; i < 16384; i += TNTH) {
                int k = i >> 8, n = i & 255;
                Ws[i] = tailW[((ch << 2) + (n >> 6)) * 4096 + (k << 6) + (n & 63)];
            }
            for (int i = tid; i < 256; i += TNTH)
                tb[i] = tailb[((ch << 2) + (i >> 6)) * 64 + (i & 63)];
            cur = ch;
        }

        zin[(k40 + 0) * ZSTR + m0s] = pf0.x;
        zin[(k40 + 1) * ZSTR + m0s] = pf0.y;
        zin[(k40 + 2) * ZSTR + m0s] = pf0.z;
        zin[(k40 + 3) * ZSTR + m0s] = pf0.w;
        zin[(k41 + 0) * ZSTR + m1s] = pf1.x;
        zin[(k41 + 1) * ZSTR + m1s] = pf1.y;
        zin[(k41 + 2) * ZSTR + m1s] = pf1.z;
        zin[(k41 + 3) * ZSTR + m1s] = pf1.w;

        if (mi + 1 < mend) {
            int tn = (mi + 1) % 12, jn = (mi + 1) / 12, btn = jn & 127;
            const float* src = g_zbuf + ((size_t)tn * BSZ + btn * SB) * 64;
            pf0 = *(const float4*)(src + m0s * 64 + k40);
            pf1 = *(const float4*)(src + m1s * 64 + k41);
        }
        __syncthreads();

        u64t acc[4][4];
        #pragma unroll
        for (int q = 0; q < 4; q++)
            acc[q][0] = acc[q][1] = acc[q][2] = acc[q][3] = 0ull;

        #pragma unroll 8
        for (int k = 0; k < 64; k++) {
            const u64t* zp = (const u64t*)(zin + k * ZSTR + (ty << 3));
            u64t z0 = zp[0], z1 = zp[1], z2 = zp[2], z3 = zp[3];
            float4 w = *(const float4*)(Ws + (k << 8) + (tx << 2));
            u64t w0 = pack2(w.x), w1 = pack2(w.y), w2 = pack2(w.z), w3 = pack2(w.w);
            fma2(acc[0][0], z0, w0); fma2(acc[0][1], z0, w1); fma2(acc[0][2], z0, w2); fma2(acc[0][3], z0, w3);
            fma2(acc[1][0], z1, w0); fma2(acc[1][1], z1, w1); fma2(acc[1][2], z1, w2); fma2(acc[1][3], z1, w3);
            fma2(acc[2][0], z2, w0); fma2(acc[2][1], z2, w1); fma2(acc[2][2], z2, w2); fma2(acc[2][3], z2, w3);
            fma2(acc[3][0], z3, w0); fma2(acc[3][1], z3, w1); fma2(acc[3][2], z3, w2); fma2(acc[3][3], z3, w3);
        }

        float4 bvv = *(const float4*)(tb + (tx << 2));
        int nt = (cur << 2) + (tx >> 4);
        int d  = (tx << 2) & 63;
        #pragma unroll
        for (int q = 0; q < 4; q++) {
            float2 r0 = unpack2(acc[q][0]), r1 = unpack2(acc[q][1]);
            float2 r2 = unpack2(acc[q][2]), r3 = unpack2(acc[q][3]);
            int mm = (ty << 3) + (q << 1);
            float* op = out + (size_t)(gb + mm) * 12288 + nt * 768 + t * 64 + d;
            *(float4*)(op)         = make_float4(r0.x + bvv.x, r1.x + bvv.y, r2.x + bvv.z, r3.x + bvv.w);
            *(float4*)(op + 12288) = make_float4(r0.y + bvv.x, r1.y + bvv.y, r2.y + bvv.z, r3.y + bvv.w);
        }
        __syncthreads();
    }
}

extern "C" void kernel_launch(void* const* d_in, const int* in_sizes, int n_in,
                              void* d_out, int out_size)
{
    cudaFuncSetAttribute(k_main, cudaFuncAttributeMaxDynamicSharedMemorySize, SMEM_MAIN);
    cudaFuncSetAttribute(k_tail, cudaFuncAttributeMaxDynamicSharedMemorySize, SMEM_TAIL);

    k_main<<<NBLK, NTH, SMEM_MAIN>>>(
        (const float*)d_in[0],  (const int*)d_in[1],
        (const float*)d_in[2],  (const float*)d_in[3],
        (const float*)d_in[4],  (const float*)d_in[5],
        (const float*)d_in[6],  (const float*)d_in[7],
        (const float*)d_in[8],  (const float*)d_in[9],
        (const float*)d_in[10], (const float*)d_in[11],
        (const float*)d_in[12], (const float*)d_in[13],
        (const float*)d_in[14], (const float*)d_in[15],
        (const float*)d_in[18]);

    k_tail<<<TGRID, TNTH, SMEM_TAIL>>>(
        (const float*)d_in[16], (const float*)d_in[17], (float*)d_out);
}